// round 7
// baseline (speedup 1.0000x reference)
#include <cuda_runtime.h>
#include <cuda_fp16.h>
#include <cstdint>
#include <math.h>

// Problem dims
#define T_STEPS 256
#define B_SZ    32
#define C_SZ    1536
#define M_SZ    1536
#define NBLK    96

#define N_ELEM_CORE (T_STEPS * B_SZ * C_SZ)   // 12,582,912

// ---------------- device scratch (static globals: no allocations) -------------
__device__ float g_u[C_SZ];
__device__ float g_v[C_SZ];
__device__ float g_t[C_SZ];
__device__ float g_scale;
__device__ float g_pre[N_ELEM_CORE];                       // x@Wx^T + b
__device__ __align__(16) __half g_Ws16[C_SZ * C_SZ];       // fp16 scaled W_h
__device__ __align__(16) __half g_Wx16[C_SZ * C_SZ];       // fp16 W_x
__device__ __align__(16) __half g_X16[N_ELEM_CORE];        // fp16 x_core
__device__ __align__(16) __half g_h16[3][B_SZ * C_SZ];     // fp16 hidden, 3-deep
__device__ unsigned g_bar_ctr;                             // grid barrier counter

// ---------------- threefry2x32 (exact JAX partitionable PRNG) ------------------
__device__ __forceinline__ uint32_t rotl32(uint32_t x, int r) {
    return (x << r) | (x >> (32 - r));
}

__device__ __forceinline__ void threefry2x32(uint32_t& x0, uint32_t& x1) {
    const uint32_t k0 = 0u, k1 = 42u;
    const uint32_t k2 = k0 ^ k1 ^ 0x1BD11BDAu;
    const uint32_t ks[3] = {k0, k1, k2};
    const int R0[4] = {13, 15, 26, 6};
    const int R1[4] = {17, 29, 16, 24};
    x0 += ks[0];
    x1 += ks[1];
#pragma unroll
    for (int i = 0; i < 5; i++) {
        const int* r = (i & 1) ? R1 : R0;
#pragma unroll
        for (int j = 0; j < 4; j++) {
            x0 += x1;
            x1 = rotl32(x1, r[j]);
            x1 ^= x0;
        }
        x0 += ks[(i + 1) % 3];
        x1 += ks[(i + 2) % 3] + (uint32_t)(i + 1);
    }
}

__device__ __forceinline__ float bits_to_normal(uint32_t bits) {
    float f = __uint_as_float((bits >> 9) | 0x3f800000u) - 1.0f;  // [0,1)
    const float lo = __uint_as_float(0xBF7FFFFFu);                // nextafter(-1,0)
    float val = __fadd_rn(__fmul_rn(f, 2.0f), lo);
    val = fmaxf(lo, val);
    return 1.41421354f * erfinvf(val);
}

// ---------------- spectral-norm kernels (fp32, verified exact) -----------------
__global__ void k_gen_u() {
    __shared__ float red[512];
    const int tid = threadIdx.x;
    float s = 0.f;
    for (int i = tid; i < C_SZ; i += 512) {
        uint32_t x0 = 0u;
        uint32_t x1 = (uint32_t)i;
        threefry2x32(x0, x1);
        uint32_t bits = x0 ^ x1;
        float n = bits_to_normal(bits);
        g_u[i] = n;
        s += n * n;
    }
    red[tid] = s;
    __syncthreads();
    for (int o = 256; o > 0; o >>= 1) {
        if (tid < o) red[tid] += red[tid + o];
        __syncthreads();
    }
    float nrm = sqrtf(red[0]);
    for (int i = tid; i < C_SZ; i += 512) g_u[i] = g_u[i] / nrm;
}

__global__ void k_mv_tn(const float* __restrict__ W, int dst) {
    const int j0 = blockIdx.x * 16;
    const int c = threadIdx.x & 15;
    const int r = threadIdx.x >> 4;
    float acc = 0.f;
    for (int i = r; i < C_SZ; i += 16)
        acc = fmaf(W[(size_t)i * C_SZ + j0 + c], g_u[i], acc);
    __shared__ float s[16][17];
    s[r][c] = acc;
    __syncthreads();
    if (r == 0) {
        float t = 0.f;
#pragma unroll
        for (int q = 0; q < 16; q++) t += s[q][c];
        if (dst == 0) g_v[j0 + c] = t;
        else          g_t[j0 + c] = t;
    }
}

__global__ void k_mv_nt(const float* __restrict__ W) {
    const int row = blockIdx.x * 32 + (threadIdx.x >> 5);
    const int lane = threadIdx.x & 31;
    float acc = 0.f;
    for (int j = lane; j < C_SZ; j += 32)
        acc = fmaf(W[(size_t)row * C_SZ + j], g_v[j], acc);
#pragma unroll
    for (int o = 16; o > 0; o >>= 1) acc += __shfl_down_sync(0xffffffffu, acc, o);
    if (lane == 0) g_t[row] = acc;
}

__global__ void k_norm_v() {
    __shared__ float red[512];
    const int tid = threadIdx.x;
    float s = 0.f;
    for (int i = tid; i < C_SZ; i += 512) { float x = g_v[i]; s += x * x; }
    red[tid] = s;
    __syncthreads();
    for (int o = 256; o > 0; o >>= 1) {
        if (tid < o) red[tid] += red[tid + o];
        __syncthreads();
    }
    float den = sqrtf(red[0]) + 1e-8f;
    for (int i = tid; i < C_SZ; i += 512) g_v[i] = g_v[i] / den;
}

__global__ void k_norm_u() {
    __shared__ float red[512];
    const int tid = threadIdx.x;
    float s = 0.f;
    for (int i = tid; i < C_SZ; i += 512) { float x = g_t[i]; s += x * x; }
    red[tid] = s;
    __syncthreads();
    for (int o = 256; o > 0; o >>= 1) {
        if (tid < o) red[tid] += red[tid + o];
        __syncthreads();
    }
    float den = sqrtf(red[0]) + 1e-8f;
    for (int i = tid; i < C_SZ; i += 512) g_u[i] = g_t[i] / den;
}

__global__ void k_sigma() {
    __shared__ float red[512];
    const int tid = threadIdx.x;
    float s = 0.f;
    for (int i = tid; i < C_SZ; i += 512) s = fmaf(g_t[i], g_v[i], s);
    red[tid] = s;
    __syncthreads();
    for (int o = 256; o > 0; o >>= 1) {
        if (tid < o) red[tid] += red[tid + o];
        __syncthreads();
    }
    if (tid == 0) {
        float sigma = fabsf(red[0]);
        g_scale = 0.99f / (sigma + 1e-8f);
    }
}

// Ws16 = fp16(W_h * scale)
__global__ void k_scaleW16(const float* __restrict__ W) {
    const float sc = g_scale;
    size_t i = (size_t)blockIdx.x * blockDim.x + threadIdx.x;
    if (i < (size_t)C_SZ * C_SZ / 2) {
        float2 v = ((const float2*)W)[i];
        ((__half2*)g_Ws16)[i] = __floats2half2_rn(v.x * sc, v.y * sc);
    }
}

// Wx16 = fp16(W_x)
__global__ void k_convWx(const float* __restrict__ W) {
    size_t i = (size_t)blockIdx.x * blockDim.x + threadIdx.x;
    if (i < (size_t)C_SZ * C_SZ / 2) {
        float2 v = ((const float2*)W)[i];
        ((__half2*)g_Wx16)[i] = __floats2half2_rn(v.x, v.y);
    }
}

// X16 = fp16(x_core)
__global__ void k_convX(const float* __restrict__ X) {
    size_t i = (size_t)blockIdx.x * blockDim.x + threadIdx.x;
    if (i < (size_t)N_ELEM_CORE / 2) {
        float2 v = ((const float2*)X)[i];
        ((__half2*)g_X16)[i] = __floats2half2_rn(v.x, v.y);
    }
}

// h16[0] = fp16(h0_core); also reset grid barrier (runs before persistent kernel)
__global__ void k_init_h16(const float* __restrict__ h0) {
    int i = blockIdx.x * blockDim.x + threadIdx.x;
    if (i == 0) g_bar_ctr = 0u;
    if (i < B_SZ * C_SZ / 2) {
        float2 v = ((const float2*)h0)[i];
        ((__half2*)g_h16[0])[i] = __floats2half2_rn(v.x, v.y);
    }
}

// ---------------- mma.sync m16n8k16 fp16 -> fp32 -------------------------------
__device__ __forceinline__ void mma16816(float* d, const uint32_t* a, const uint32_t* b) {
    asm volatile(
        "mma.sync.aligned.m16n8k16.row.col.f32.f16.f16.f32 "
        "{%0,%1,%2,%3},{%4,%5,%6,%7},{%8,%9},{%0,%1,%2,%3};"
        : "+f"(d[0]), "+f"(d[1]), "+f"(d[2]), "+f"(d[3])
        : "r"(a[0]), "r"(a[1]), "r"(a[2]), "r"(a[3]), "r"(b[0]), "r"(b[1]));
}

// ---------------- phase-1 GEMM: pre = X @ Wx^T + b (fp16 TC) -------------------
__global__ void k_gemm16(const float* __restrict__ bc) {
    __shared__ __half As[64][72];
    __shared__ __half Bs[64][72];
    const int bm = blockIdx.y * 64;
    const int bn = blockIdx.x * 64;
    const int tid = threadIdx.x;
    const int w = tid >> 5;
    const int lane = tid & 31;
    const int wm = w >> 1, wn = w & 1;
    const int g = lane >> 2, tg = lane & 3;

    const __half* X = g_X16;
    const __half* Wx = g_Wx16;

    float acc[2][4][4];
#pragma unroll
    for (int i = 0; i < 2; i++)
#pragma unroll
        for (int j = 0; j < 4; j++)
#pragma unroll
            for (int q = 0; q < 4; q++) acc[i][j][q] = 0.f;

    for (int k0 = 0; k0 < C_SZ; k0 += 64) {
#pragma unroll
        for (int it = 0; it < 4; it++) {
            int i = tid + it * 128;
            int r = i >> 3;
            int c = (i & 7) * 8;
            *(float4*)&As[r][c] = *(const float4*)&X[(size_t)(bm + r) * C_SZ + k0 + c];
            *(float4*)&Bs[r][c] = *(const float4*)&Wx[(size_t)(bn + r) * C_SZ + k0 + c];
        }
        __syncthreads();
#pragma unroll
        for (int kt = 0; kt < 4; kt++) {
            int k = kt * 16;
            uint32_t a[2][4], b[4][2];
#pragma unroll
            for (int mi = 0; mi < 2; mi++) {
                int r0 = wm * 32 + mi * 16 + g;
                a[mi][0] = *(const uint32_t*)&As[r0][k + 2 * tg];
                a[mi][1] = *(const uint32_t*)&As[r0 + 8][k + 2 * tg];
                a[mi][2] = *(const uint32_t*)&As[r0][k + 2 * tg + 8];
                a[mi][3] = *(const uint32_t*)&As[r0 + 8][k + 2 * tg + 8];
            }
#pragma unroll
            for (int ni = 0; ni < 4; ni++) {
                int r0 = wn * 32 + ni * 8 + g;
                b[ni][0] = *(const uint32_t*)&Bs[r0][k + 2 * tg];
                b[ni][1] = *(const uint32_t*)&Bs[r0][k + 2 * tg + 8];
            }
#pragma unroll
            for (int mi = 0; mi < 2; mi++)
#pragma unroll
                for (int ni = 0; ni < 4; ni++)
                    mma16816(acc[mi][ni], a[mi], b[ni]);
        }
        __syncthreads();
    }

#pragma unroll
    for (int mi = 0; mi < 2; mi++) {
        int row = bm + wm * 32 + mi * 16 + g;
#pragma unroll
        for (int ni = 0; ni < 4; ni++) {
            int col = bn + wn * 32 + ni * 8 + 2 * tg;
            float b0 = bc[col], b1 = bc[col + 1];
            float2 o0 = make_float2(acc[mi][ni][0] + b0, acc[mi][ni][1] + b1);
            float2 o1 = make_float2(acc[mi][ni][2] + b0, acc[mi][ni][3] + b1);
            *(float2*)&g_pre[(size_t)row * C_SZ + col] = o0;
            *(float2*)&g_pre[(size_t)(row + 8) * C_SZ + col] = o1;
        }
    }
}

// ---------------- persistent recurrence kernel ---------------------------------
// 96 blocks x 256 threads, 1/SM. Block owns 16 output cols for all 256 steps.
// W fragments live in REGISTERS for the whole kernel (step-invariant).
// h fragments are loaded global->register with ld.cg (L2-coherent, no L1 risk).
__global__ void __launch_bounds__(256, 1)
k_recurrent(const float* __restrict__ zc,
            float* __restrict__ out_core,
            float* __restrict__ h_core_f) {
    __shared__ float red[8 * 512];   // warp partials [8][512]

    const int n0 = blockIdx.x * 16;
    const int tid = threadIdx.x;
    const int w = tid >> 5;
    const int lane = tid & 31;
    const int g = lane >> 2, tg = lane & 3;
    const int kbase = w * 192;

    // ---- load W fragments once into registers (48 regs) ----
    uint32_t bf[12][2][2];
#pragma unroll
    for (int kt = 0; kt < 12; kt++) {
        int k0 = kbase + kt * 16 + 2 * tg;
#pragma unroll
        for (int ni = 0; ni < 2; ni++) {
            const __half* wr = g_Ws16 + (size_t)(n0 + ni * 8 + g) * C_SZ;
            bf[kt][ni][0] = *(const uint32_t*)(wr + k0);
            bf[kt][ni][1] = *(const uint32_t*)(wr + k0 + 8);
        }
    }

    // output pair mapping: outputs o0=2*tid, o0+1 -> batch ob, cols oc, oc+1
    const int o0 = 2 * tid;
    const int ob = o0 >> 4;
    const int occ = o0 & 15;
    const int oc = n0 + occ;

    for (int t = 0; t < T_STEPS; t++) {
        const __half* hb = g_h16[t % 3];
        __half* hn = g_h16[(t + 1) % 3];
        const size_t base = (size_t)t * B_SZ * C_SZ;
        const size_t oidx = base + (size_t)ob * C_SZ + oc;

        // issue pre/z loads early (independent of h / barrier)
        float2 pre2 = *(const float2*)&g_pre[oidx];
        float2 z2 = *(const float2*)&zc[oidx];

        // 4 h-row base pointers for this warp's fragments
        const __half* h0p = hb + (size_t)g * C_SZ + kbase + 2 * tg;
        const __half* h1p = h0p + 8 * C_SZ;
        const __half* h2p = h0p + 16 * C_SZ;
        const __half* h3p = h0p + 24 * C_SZ;

        float acc[2][2][4];
#pragma unroll
        for (int i = 0; i < 2; i++)
#pragma unroll
            for (int j = 0; j < 2; j++)
#pragma unroll
                for (int q = 0; q < 4; q++) acc[i][j][q] = 0.f;

#pragma unroll
        for (int kt = 0; kt < 12; kt++) {
            const int k = kt * 16;
            uint32_t a0[4], a1[4];
            a0[0] = __ldcg((const uint32_t*)(h0p + k));
            a0[1] = __ldcg((const uint32_t*)(h1p + k));
            a0[2] = __ldcg((const uint32_t*)(h0p + k + 8));
            a0[3] = __ldcg((const uint32_t*)(h1p + k + 8));
            a1[0] = __ldcg((const uint32_t*)(h2p + k));
            a1[1] = __ldcg((const uint32_t*)(h3p + k));
            a1[2] = __ldcg((const uint32_t*)(h2p + k + 8));
            a1[3] = __ldcg((const uint32_t*)(h3p + k + 8));
#pragma unroll
            for (int ni = 0; ni < 2; ni++) {
                mma16816(acc[0][ni], a0, bf[kt][ni]);
                mma16816(acc[1][ni], a1, bf[kt][ni]);
            }
        }

        // write warp partials: flat index = row(b)*16 + local col
#pragma unroll
        for (int mi = 0; mi < 2; mi++)
#pragma unroll
            for (int ni = 0; ni < 2; ni++) {
                int r0 = mi * 16 + g;
                int c0 = ni * 8 + 2 * tg;
                *(float2*)&red[w * 512 + r0 * 16 + c0] =
                    make_float2(acc[mi][ni][0], acc[mi][ni][1]);
                *(float2*)&red[w * 512 + (r0 + 8) * 16 + c0] =
                    make_float2(acc[mi][ni][2], acc[mi][ni][3]);
            }
        __syncthreads();

        // reduce 8 warp partials for output pair
        float s0 = 0.f, s1 = 0.f;
#pragma unroll
        for (int q = 0; q < 8; q++) {
            float2 v = *(const float2*)&red[q * 512 + o0];
            s0 += v.x;
            s1 += v.y;
        }
        float hv0 = tanhf(pre2.x + s0);
        float hv1 = tanhf(pre2.y + s1);
        *(__half2*)&hn[ob * C_SZ + oc] = __floats2half2_rn(hv0, hv1);
        __syncthreads();              // all h_next stores block-wide before arrive

        // barrier ARRIVE (release)
        if (tid == 0) {
            __threadfence();
            atomicAdd(&g_bar_ctr, 1u);
        }

        // epilogue overlapped with other blocks' arrival (silu: output-only)
        {
            float sl0 = z2.x * (1.0f / (1.0f + __expf(-z2.x)));
            float sl1 = z2.y * (1.0f / (1.0f + __expf(-z2.y)));
            *(float2*)&out_core[oidx] = make_float2(hv0 * sl0, hv1 * sl1);
        }
        if (t == T_STEPS - 1)
            *(float2*)&h_core_f[ob * C_SZ + oc] = make_float2(hv0, hv1);

        // barrier WAIT (acquire)
        if (tid == 0) {
            const unsigned target = (unsigned)(NBLK * (t + 1));
            unsigned v;
            do {
                asm volatile("ld.acquire.gpu.u32 %0, [%1];"
                             : "=r"(v) : "l"(&g_bar_ctr));
            } while (v < target);
        }
        __syncthreads();
    }
}

// ---------------- memory branch (independent scan, 4-deep prefetch) -------------
__global__ void k_mem(const float* __restrict__ xm, const float* __restrict__ zm,
                      const float* __restrict__ h0, const float* __restrict__ am,
                      float* __restrict__ out_mem, float* __restrict__ h_mem_f) {
    const int gid = blockIdx.x * blockDim.x + threadIdx.x;  // 0..49151
    const int m = gid & (M_SZ - 1);
    const float a = am[m];
    const float decay = 1.0f / (1.0f + expf(-a));
    float h = h0[gid];
    const size_t stride = (size_t)B_SZ * M_SZ;

    float xs[4], zs[4];
#pragma unroll
    for (int q = 0; q < 4; q++) {
        xs[q] = xm[gid + q * stride];
        zs[q] = zm[gid + q * stride];
    }
    size_t off = gid;
    for (int t0 = 0; t0 < T_STEPS; t0 += 4) {
        float xn[4], zn[4];
        if (t0 + 4 < T_STEPS) {
            size_t poff = off + 4 * stride;
#pragma unroll
            for (int q = 0; q < 4; q++) {
                xn[q] = xm[poff + q * stride];
                zn[q] = zm[poff + q * stride];
            }
        }
#pragma unroll
        for (int q = 0; q < 4; q++) {
            h = fmaf(decay, h, xs[q]);
            float z = zs[q];
            out_mem[off + q * stride] = h * (z * (1.0f / (1.0f + expf(-z))));
        }
#pragma unroll
        for (int q = 0; q < 4; q++) { xs[q] = xn[q]; zs[q] = zn[q]; }
        off += 4 * stride;
    }
    h_mem_f[gid] = h;
}

// ---------------- launch --------------------------------------------------------
extern "C" void kernel_launch(void* const* d_in, const int* in_sizes, int n_in,
                              void* d_out, int out_size) {
    const float* x_core  = (const float*)d_in[0];
    const float* z_core  = (const float*)d_in[1];
    const float* x_mem   = (const float*)d_in[2];
    const float* z_mem   = (const float*)d_in[3];
    const float* h0_core = (const float*)d_in[4];
    const float* h0_mem  = (const float*)d_in[5];
    const float* W_x     = (const float*)d_in[6];
    const float* W_h     = (const float*)d_in[7];
    const float* b_core  = (const float*)d_in[8];
    const float* a_mem   = (const float*)d_in[9];

    float* out       = (float*)d_out;
    float* out_core  = out;
    float* out_mem   = out + (size_t)T_STEPS * B_SZ * C_SZ;
    float* h_core_f  = out_mem + (size_t)T_STEPS * B_SZ * M_SZ;
    float* h_mem_f   = h_core_f + (size_t)B_SZ * C_SZ;

    // spectral norm of W_h -> g_scale
    k_gen_u<<<1, 512>>>();
    for (int it = 0; it < 3; it++) {
        k_mv_tn<<<96, 256>>>(W_h, 0);
        k_norm_v<<<1, 512>>>();
        k_mv_nt<<<48, 1024>>>(W_h);
        k_norm_u<<<1, 512>>>();
    }
    k_mv_tn<<<96, 256>>>(W_h, 1);   // g_t = u @ W
    k_sigma<<<1, 512>>>();

    // fp16 conversions (device globals referenced only in device code)
    k_scaleW16<<<(C_SZ * C_SZ / 2 + 255) / 256, 256>>>(W_h);
    k_convWx<<<(C_SZ * C_SZ / 2 + 255) / 256, 256>>>(W_x);
    k_convX<<<(N_ELEM_CORE / 2 + 255) / 256, 256>>>(x_core);
    k_init_h16<<<(B_SZ * C_SZ / 2 + 255) / 256, 256>>>(h0_core);

    // pre = x_core @ W_x^T + b_core (tensor cores)
    {
        dim3 grid(C_SZ / 64, (T_STEPS * B_SZ) / 64);  // (24, 128)
        k_gemm16<<<grid, 128>>>(b_core);
    }

    // memory branch (independent)
    k_mem<<<192, 256>>>(x_mem, z_mem, h0_mem, a_mem, out_mem, h_mem_f);

    // persistent recurrence over all 256 steps
    k_recurrent<<<NBLK, 256>>>(z_core, out_core, h_core_f);
}

// round 8
// speedup vs baseline: 1.5811x; 1.5811x over previous
#include <cuda_runtime.h>
#include <cuda_fp16.h>
#include <cstdint>
#include <math.h>

// Problem dims
#define T_STEPS 256
#define B_SZ    32
#define C_SZ    1536
#define M_SZ    1536
#define NBLK    96

#define N_ELEM_CORE (T_STEPS * B_SZ * C_SZ)   // 12,582,912

// ---------------- device scratch (static globals: no allocations) -------------
__device__ float g_v[C_SZ];                                // raw v (power iter)
__device__ float g_t[C_SZ];                                // real t / w vector
__device__ float g_pre[N_ELEM_CORE];                       // x@Wx^T + b
__device__ __align__(16) __half g_Ws16[C_SZ * C_SZ];       // fp16 scaled W_h
__device__ __align__(16) __half g_Wx16[C_SZ * C_SZ];       // fp16 W_x
__device__ __align__(16) __half g_X16[N_ELEM_CORE];        // fp16 x_core
__device__ __align__(16) __half g_h16[3][B_SZ * C_SZ];     // fp16 hidden, 3-deep
__device__ unsigned g_bar_ctr;                             // barrier (recurrent)
__device__ unsigned g_bar2;                                // barrier (prep)

// ---------------- threefry2x32 (exact JAX partitionable PRNG) ------------------
__device__ __forceinline__ uint32_t rotl32(uint32_t x, int r) {
    return (x << r) | (x >> (32 - r));
}

__device__ __forceinline__ void threefry2x32(uint32_t& x0, uint32_t& x1) {
    const uint32_t k0 = 0u, k1 = 42u;
    const uint32_t k2 = k0 ^ k1 ^ 0x1BD11BDAu;
    const uint32_t ks[3] = {k0, k1, k2};
    const int R0[4] = {13, 15, 26, 6};
    const int R1[4] = {17, 29, 16, 24};
    x0 += ks[0];
    x1 += ks[1];
#pragma unroll
    for (int i = 0; i < 5; i++) {
        const int* r = (i & 1) ? R1 : R0;
#pragma unroll
        for (int j = 0; j < 4; j++) {
            x0 += x1;
            x1 = rotl32(x1, r[j]);
            x1 ^= x0;
        }
        x0 += ks[(i + 1) % 3];
        x1 += ks[(i + 2) % 3] + (uint32_t)(i + 1);
    }
}

__device__ __forceinline__ float bits_to_normal(uint32_t bits) {
    float f = __uint_as_float((bits >> 9) | 0x3f800000u) - 1.0f;  // [0,1)
    const float lo = __uint_as_float(0xBF7FFFFFu);                // nextafter(-1,0)
    float val = __fadd_rn(__fmul_rn(f, 2.0f), lo);
    val = fmaxf(lo, val);
    return 1.41421354f * erfinvf(val);
}

// ---------------- small helpers -------------------------------------------------
__global__ void k_reset_bar() { g_bar_ctr = 0u; g_bar2 = 0u; }

// deterministic block-wide sum, result broadcast to all threads
__device__ __forceinline__ float block_sum(float v, float* red2) {
    const int tid = threadIdx.x;
    __syncthreads();                 // protect previous red2 use
    red2[tid] = v;
    __syncthreads();
    for (int o = 128; o > 0; o >>= 1) {
        if (tid < o) red2[tid] += red2[tid + o];
        __syncthreads();
    }
    return red2[0];
}

__device__ __forceinline__ void gbar2(int phase) {
    __syncthreads();
    if (threadIdx.x == 0) {
        __threadfence();
        atomicAdd(&g_bar2, 1u);
        const unsigned tgt = (unsigned)(phase * NBLK);
        unsigned v;
        do {
            asm volatile("ld.acquire.gpu.u32 %0, [%1];" : "=r"(v) : "l"(&g_bar2));
        } while (v < tgt);
    }
    __syncthreads();
}

// ---------------- fused prep kernel ---------------------------------------------
// 96 blocks x 256 threads. Does: u-gen, 3 power iterations (2 grid barriers each),
// final w = W^T u, sigma, then all fp16 conversions + h0 init.
// All scalar reductions are computed redundantly per block (deterministic).
__global__ void __launch_bounds__(256, 1)
k_prep(const float* __restrict__ Wh, const float* __restrict__ Wx,
       const float* __restrict__ X, const float* __restrict__ h0) {
    __shared__ float usm[C_SZ];      // current u (normalized)
    __shared__ float xsm[C_SZ];      // scratch vector (v or t copy)
    __shared__ float red2[256];
    __shared__ float sbuf[16][17];

    const int tid = threadIdx.x;
    const int blk = blockIdx.x;
    int phase = 0;

    // ---- P0: generate u (partitionable threefry), normalize by /nrm ----
    {
        float ss = 0.f;
        for (int i = tid; i < C_SZ; i += 256) {
            uint32_t x0 = 0u, x1 = (uint32_t)i;
            threefry2x32(x0, x1);
            float n = bits_to_normal(x0 ^ x1);
            usm[i] = n;
            ss += n * n;
        }
        float s2 = block_sum(ss, red2);
        float nrm = sqrtf(s2);
        __syncthreads();
        for (int i = tid; i < C_SZ; i += 256) usm[i] = usm[i] / nrm;
        __syncthreads();
    }

    // ---- 3 power iterations ----
    for (int it = 0; it < 3; it++) {
        // A: v_raw[16 cols] = W^T u   (block owns cols j0..j0+15)
        {
            const int j0 = blk * 16;
            const int c = tid & 15, r = tid >> 4;
            float acc = 0.f;
            for (int i = r; i < C_SZ; i += 16)
                acc = fmaf(Wh[(size_t)i * C_SZ + j0 + c], usm[i], acc);
            sbuf[r][c] = acc;
            __syncthreads();
            if (r == 0) {
                float t = 0.f;
#pragma unroll
                for (int q = 0; q < 16; q++) t += sbuf[q][c];
                g_v[j0 + c] = t;
            }
        }
        gbar2(++phase);

        // B: s_v = 1/(||v_raw||+eps); t_real[16 rows] = (W v_raw) * s_v
        {
            float p = 0.f;
            for (int i = tid; i < C_SZ; i += 256) {
                float x = g_v[i];
                xsm[i] = x;
                p += x * x;
            }
            float s2 = block_sum(p, red2);
            float s_v = 1.0f / (sqrtf(s2) + 1e-8f);
            __syncthreads();
            const int i0 = blk * 16;
            const int r2 = tid >> 4, c = tid & 15;
            float acc = 0.f;
            for (int j = c; j < C_SZ; j += 16)
                acc = fmaf(Wh[(size_t)(i0 + r2) * C_SZ + j], xsm[j], acc);
            sbuf[r2][c] = acc;
            __syncthreads();
            if (c == 0) {
                float t = 0.f;
#pragma unroll
                for (int q = 0; q < 16; q++) t += sbuf[r2][q];
                g_t[i0 + r2] = t * s_v;
            }
        }
        gbar2(++phase);

        // C: u = t_real / (||t_real||+eps)   (local; every block computes full u)
        {
            float p = 0.f;
            for (int i = tid; i < C_SZ; i += 256) {
                float x = g_t[i];
                xsm[i] = x;
                p += x * x;
            }
            float s2 = block_sum(p, red2);
            float inv = 1.0f / (sqrtf(s2) + 1e-8f);
            __syncthreads();
            for (int i = tid; i < C_SZ; i += 256) usm[i] = xsm[i] * inv;
            __syncthreads();
        }
    }

    // ---- final: w = W^T u  -> g_t ----
    {
        const int j0 = blk * 16;
        const int c = tid & 15, r = tid >> 4;
        float acc = 0.f;
        for (int i = r; i < C_SZ; i += 16)
            acc = fmaf(Wh[(size_t)i * C_SZ + j0 + c], usm[i], acc);
        sbuf[r][c] = acc;
        __syncthreads();
        if (r == 0) {
            float t = 0.f;
#pragma unroll
            for (int q = 0; q < 16; q++) t += sbuf[q][c];
            g_t[j0 + c] = t;
        }
    }
    gbar2(++phase);   // phase 7

    // ---- sigma = |w . (v_raw * s_v)| ; scale = 0.99/(sigma+eps) ----
    float pd = 0.f, pv = 0.f;
    for (int i = tid; i < C_SZ; i += 256) {
        float wv = g_t[i];
        float vv = g_v[i];
        pd = fmaf(wv, vv, pd);
        pv = fmaf(vv, vv, pv);
    }
    float dot = block_sum(pd, red2);
    float sv2 = block_sum(pv, red2);
    float s_v = 1.0f / (sqrtf(sv2) + 1e-8f);
    float sigma = fabsf(dot * s_v);
    float scale = 0.99f / (sigma + 1e-8f);

    // ---- conversions (grid-stride; no barriers needed) ----
    const size_t start = (size_t)blk * 256 + tid;
    const size_t stride = (size_t)NBLK * 256;             // 24576
    const float2* Wh2 = (const float2*)Wh;
    const float2* Wx2 = (const float2*)Wx;
    const float2* X2 = (const float2*)X;
    for (size_t i = start; i < (size_t)C_SZ * C_SZ / 2; i += stride) {
        float2 v = Wh2[i];
        ((__half2*)g_Ws16)[i] = __floats2half2_rn(v.x * scale, v.y * scale);
        float2 u = Wx2[i];
        ((__half2*)g_Wx16)[i] = __floats2half2_rn(u.x, u.y);
    }
    for (size_t i = start; i < (size_t)N_ELEM_CORE / 2; i += stride) {
        float2 v = X2[i];
        ((__half2*)g_X16)[i] = __floats2half2_rn(v.x, v.y);
    }
    {
        // B*C/2 = 24576 == stride : exactly one element per thread
        float2 v = ((const float2*)h0)[start];
        ((__half2*)g_h16[0])[start] = __floats2half2_rn(v.x, v.y);
    }
}

// ---------------- mma.sync m16n8k16 fp16 -> fp32 -------------------------------
__device__ __forceinline__ void mma16816(float* d, const uint32_t* a, const uint32_t* b) {
    asm volatile(
        "mma.sync.aligned.m16n8k16.row.col.f32.f16.f16.f32 "
        "{%0,%1,%2,%3},{%4,%5,%6,%7},{%8,%9},{%0,%1,%2,%3};"
        : "+f"(d[0]), "+f"(d[1]), "+f"(d[2]), "+f"(d[3])
        : "r"(a[0]), "r"(a[1]), "r"(a[2]), "r"(a[3]), "r"(b[0]), "r"(b[1]));
}

__device__ __forceinline__ void ldsm4(uint32_t* r, uint32_t saddr) {
    asm volatile("ldmatrix.sync.aligned.m8n8.x4.shared.b16 {%0,%1,%2,%3}, [%4];"
                 : "=r"(r[0]), "=r"(r[1]), "=r"(r[2]), "=r"(r[3]) : "r"(saddr));
}

// ---------------- phase-1 GEMM: pre = X @ Wx^T + b (fp16 TC, 128x64 tile) ------
__global__ void __launch_bounds__(256) k_gemm16(const float* __restrict__ bc) {
    __shared__ __half As[128][72];
    __shared__ __half Bs[64][72];
    const int bm = blockIdx.y * 128;
    const int bn = blockIdx.x * 64;
    const int tid = threadIdx.x;
    const int w = tid >> 5;
    const int lane = tid & 31;
    const int wm = w >> 1, wn = w & 1;     // wm 0..3, wn 0..1
    const int g = lane >> 2, tg = lane & 3;

    const __half* X = g_X16;
    const __half* Wx = g_Wx16;

    float acc[2][4][4];
#pragma unroll
    for (int i = 0; i < 2; i++)
#pragma unroll
        for (int j = 0; j < 4; j++)
#pragma unroll
            for (int q = 0; q < 4; q++) acc[i][j][q] = 0.f;

    for (int k0 = 0; k0 < C_SZ; k0 += 64) {
#pragma unroll
        for (int it = 0; it < 4; it++) {
            int i = tid + it * 256;        // 0..1023
            int r = i >> 3;                // 0..127
            int c = (i & 7) * 8;
            *(float4*)&As[r][c] = *(const float4*)&X[(size_t)(bm + r) * C_SZ + k0 + c];
        }
#pragma unroll
        for (int it = 0; it < 2; it++) {
            int i = tid + it * 256;        // 0..511
            int r = i >> 3;                // 0..63
            int c = (i & 7) * 8;
            *(float4*)&Bs[r][c] = *(const float4*)&Wx[(size_t)(bn + r) * C_SZ + k0 + c];
        }
        __syncthreads();
#pragma unroll
        for (int kt = 0; kt < 4; kt++) {
            int k = kt * 16;
            uint32_t a[2][4], b[4][2];
#pragma unroll
            for (int mi = 0; mi < 2; mi++) {
                int r0 = wm * 32 + mi * 16 + g;
                a[mi][0] = *(const uint32_t*)&As[r0][k + 2 * tg];
                a[mi][1] = *(const uint32_t*)&As[r0 + 8][k + 2 * tg];
                a[mi][2] = *(const uint32_t*)&As[r0][k + 2 * tg + 8];
                a[mi][3] = *(const uint32_t*)&As[r0 + 8][k + 2 * tg + 8];
            }
#pragma unroll
            for (int ni = 0; ni < 4; ni++) {
                int r0 = wn * 32 + ni * 8 + g;
                b[ni][0] = *(const uint32_t*)&Bs[r0][k + 2 * tg];
                b[ni][1] = *(const uint32_t*)&Bs[r0][k + 2 * tg + 8];
            }
#pragma unroll
            for (int mi = 0; mi < 2; mi++)
#pragma unroll
                for (int ni = 0; ni < 4; ni++)
                    mma16816(acc[mi][ni], a[mi], b[ni]);
        }
        __syncthreads();
    }

#pragma unroll
    for (int mi = 0; mi < 2; mi++) {
        int row = bm + wm * 32 + mi * 16 + g;
#pragma unroll
        for (int ni = 0; ni < 4; ni++) {
            int col = bn + wn * 32 + ni * 8 + 2 * tg;
            float b0 = bc[col], b1 = bc[col + 1];
            float2 o0 = make_float2(acc[mi][ni][0] + b0, acc[mi][ni][1] + b1);
            float2 o1 = make_float2(acc[mi][ni][2] + b0, acc[mi][ni][3] + b1);
            *(float2*)&g_pre[(size_t)row * C_SZ + col] = o0;
            *(float2*)&g_pre[(size_t)(row + 8) * C_SZ + col] = o1;
        }
    }
}

// ---------------- persistent recurrence kernel ---------------------------------
// 96 blocks x 256 threads, 1/SM. Block owns 16 output cols for all 256 steps.
// W fragments in registers (loaded once). h staged to smem via ld.cg, fragments
// extracted with ldmatrix.x4.
#define SH 1544                                    // padded half stride
#define SMEM_R (32 * SH * 2 + 8 * 512 * 4)         // h tile + reduction buffer

__global__ void __launch_bounds__(256, 1)
k_recurrent(const float* __restrict__ zc,
            float* __restrict__ out_core,
            float* __restrict__ h_core_f) {
    extern __shared__ __align__(16) char smem[];
    __half* hsm = (__half*)smem;                        // [32][SH]
    float* red = (float*)(smem + 32 * SH * 2);          // [8][512]

    const int n0 = blockIdx.x * 16;
    const int tid = threadIdx.x;
    const int w = tid >> 5;
    const int lane = tid & 31;
    const int g = lane >> 2, tg = lane & 3;
    const int kbase = w * 192;

    // ---- W fragments once into registers (48 regs) ----
    uint32_t bf[12][2][2];
#pragma unroll
    for (int kt = 0; kt < 12; kt++) {
        int k0 = kbase + kt * 16 + 2 * tg;
#pragma unroll
        for (int ni = 0; ni < 2; ni++) {
            const __half* wr = g_Ws16 + (size_t)(n0 + ni * 8 + g) * C_SZ;
            bf[kt][ni][0] = *(const uint32_t*)(wr + k0);
            bf[kt][ni][1] = *(const uint32_t*)(wr + k0 + 8);
        }
    }

    // ldmatrix lane address bases (bytes, shared space)
    const uint32_t hsm_s = (uint32_t)__cvta_generic_to_shared(hsm);
    const int lrow = lane & 15;                 // 0..15
    const int lcol = (lane >> 4) * 8;           // 0 or 8 halves
    const uint32_t a_base0 = hsm_s + (uint32_t)((lrow * SH + lcol + kbase) * 2);
    const uint32_t a_base1 = a_base0 + (uint32_t)(16 * SH * 2);

    // output pair mapping
    const int o0 = 2 * tid;
    const int ob = o0 >> 4;
    const int oc = n0 + (o0 & 15);

    for (int t = 0; t < T_STEPS; t++) {
        const __half* hb = g_h16[t % 3];
        __half* hn = g_h16[(t + 1) % 3];
        const size_t base = (size_t)t * B_SZ * C_SZ;
        const size_t oidx = base + (size_t)ob * C_SZ + oc;

        // independent loads issued early
        float2 pre2 = *(const float2*)&g_pre[oidx];
        float2 z2 = *(const float2*)&zc[oidx];

        // stage h (6144 float4) via ld.cg (L2-coherent)
#pragma unroll
        for (int it = 0; it < 24; it++) {
            int i = tid + it * 256;
            int r = i / 192, c = (i % 192) * 8;
            float4 v = __ldcg(&((const float4*)hb)[i]);
            *(float4*)&hsm[r * SH + c] = v;
        }
        __syncthreads();

        float acc[2][2][4];
#pragma unroll
        for (int i = 0; i < 2; i++)
#pragma unroll
            for (int j = 0; j < 2; j++)
#pragma unroll
                for (int q = 0; q < 4; q++) acc[i][j][q] = 0.f;

#pragma unroll
        for (int kt = 0; kt < 12; kt++) {
            const uint32_t koff = (uint32_t)(kt * 32);   // 16 halves
            uint32_t a0[4], a1[4];
            ldsm4(a0, a_base0 + koff);
            ldsm4(a1, a_base1 + koff);
#pragma unroll
            for (int ni = 0; ni < 2; ni++) {
                mma16816(acc[0][ni], a0, bf[kt][ni]);
                mma16816(acc[1][ni], a1, bf[kt][ni]);
            }
        }

        // warp partials
#pragma unroll
        for (int mi = 0; mi < 2; mi++)
#pragma unroll
            for (int ni = 0; ni < 2; ni++) {
                int r0 = mi * 16 + g;
                int c0 = ni * 8 + 2 * tg;
                *(float2*)&red[w * 512 + r0 * 16 + c0] =
                    make_float2(acc[mi][ni][0], acc[mi][ni][1]);
                *(float2*)&red[w * 512 + (r0 + 8) * 16 + c0] =
                    make_float2(acc[mi][ni][2], acc[mi][ni][3]);
            }
        __syncthreads();

        // reduce, tanh, store h_next
        float s0 = 0.f, s1 = 0.f;
#pragma unroll
        for (int q = 0; q < 8; q++) {
            float2 v = *(const float2*)&red[q * 512 + o0];
            s0 += v.x;
            s1 += v.y;
        }
        float hv0 = tanhf(pre2.x + s0);
        float hv1 = tanhf(pre2.y + s1);
        *(__half2*)&hn[ob * C_SZ + oc] = __floats2half2_rn(hv0, hv1);
        __syncthreads();           // all block stores issued before release

        // barrier ARRIVE (release)
        if (tid == 0) {
            __threadfence();
            atomicAdd(&g_bar_ctr, 1u);
        }

        // epilogue hidden in barrier slack
        {
            float sl0 = z2.x * (1.0f / (1.0f + __expf(-z2.x)));
            float sl1 = z2.y * (1.0f / (1.0f + __expf(-z2.y)));
            *(float2*)&out_core[oidx] = make_float2(hv0 * sl0, hv1 * sl1);
        }
        if (t == T_STEPS - 1)
            *(float2*)&h_core_f[ob * C_SZ + oc] = make_float2(hv0, hv1);

        // barrier WAIT (acquire)
        if (tid == 0) {
            const unsigned target = (unsigned)(NBLK * (t + 1));
            unsigned v;
            do {
                asm volatile("ld.acquire.gpu.u32 %0, [%1];"
                             : "=r"(v) : "l"(&g_bar_ctr));
            } while (v < target);
        }
        __syncthreads();
    }
}

// ---------------- memory branch (independent scan, 4-deep prefetch) -------------
__global__ void k_mem(const float* __restrict__ xm, const float* __restrict__ zm,
                      const float* __restrict__ h0, const float* __restrict__ am,
                      float* __restrict__ out_mem, float* __restrict__ h_mem_f) {
    const int gid = blockIdx.x * blockDim.x + threadIdx.x;  // 0..49151
    const int m = gid & (M_SZ - 1);
    const float a = am[m];
    const float decay = 1.0f / (1.0f + expf(-a));
    float h = h0[gid];
    const size_t stride = (size_t)B_SZ * M_SZ;

    float xs[4], zs[4];
#pragma unroll
    for (int q = 0; q < 4; q++) {
        xs[q] = xm[gid + q * stride];
        zs[q] = zm[gid + q * stride];
    }
    size_t off = gid;
    for (int t0 = 0; t0 < T_STEPS; t0 += 4) {
        float xn[4], zn[4];
        const bool more = (t0 + 4 < T_STEPS);
        if (more) {
            size_t poff = off + 4 * stride;
#pragma unroll
            for (int q = 0; q < 4; q++) {
                xn[q] = xm[poff + q * stride];
                zn[q] = zm[poff + q * stride];
            }
        }
#pragma unroll
        for (int q = 0; q < 4; q++) {
            h = fmaf(decay, h, xs[q]);
            float z = zs[q];
            out_mem[off + q * stride] = h * (z * (1.0f / (1.0f + expf(-z))));
        }
        if (more) {
#pragma unroll
            for (int q = 0; q < 4; q++) { xs[q] = xn[q]; zs[q] = zn[q]; }
        }
        off += 4 * stride;
    }
    h_mem_f[gid] = h;
}

// ---------------- launch --------------------------------------------------------
extern "C" void kernel_launch(void* const* d_in, const int* in_sizes, int n_in,
                              void* d_out, int out_size) {
    const float* x_core  = (const float*)d_in[0];
    const float* z_core  = (const float*)d_in[1];
    const float* x_mem   = (const float*)d_in[2];
    const float* z_mem   = (const float*)d_in[3];
    const float* h0_core = (const float*)d_in[4];
    const float* h0_mem  = (const float*)d_in[5];
    const float* W_x     = (const float*)d_in[6];
    const float* W_h     = (const float*)d_in[7];
    const float* b_core  = (const float*)d_in[8];
    const float* a_mem   = (const float*)d_in[9];

    float* out       = (float*)d_out;
    float* out_core  = out;
    float* out_mem   = out + (size_t)T_STEPS * B_SZ * C_SZ;
    float* h_core_f  = out_mem + (size_t)T_STEPS * B_SZ * M_SZ;
    float* h_mem_f   = h_core_f + (size_t)B_SZ * C_SZ;

    cudaFuncSetAttribute(k_recurrent, cudaFuncAttributeMaxDynamicSharedMemorySize,
                         SMEM_R);

    // reset both grid-barrier counters
    k_reset_bar<<<1, 1>>>();

    // fused spectral norm + fp16 conversions + h0 init
    k_prep<<<NBLK, 256>>>(W_h, W_x, x_core, h0_core);

    // pre = x_core @ W_x^T + b_core (tensor cores, 128x64 tiles)
    {
        dim3 grid(C_SZ / 64, (T_STEPS * B_SZ) / 128);  // (24, 64)
        k_gemm16<<<grid, 256>>>(b_core);
    }

    // memory branch (independent)
    k_mem<<<192, 256>>>(x_mem, z_mem, h0_mem, a_mem, out_mem, h_mem_f);

    // persistent recurrence over all 256 steps
    k_recurrent<<<NBLK, 256, SMEM_R>>>(z_core, out_core, h_core_f);
}